// round 15
// baseline (speedup 1.0000x reference)
#include <cuda_runtime.h>
#include <cuda_fp16.h>
#include <mma.h>
#include <cstdint>

using namespace nvcuda;

#define BB 4
#define NN 8192
#define DD 16
#define RR 32
#define HH 64
#define EE 262144

// Scratch (allocation-free: __device__ globals)
__device__ __half g_P1h[BB * NN * HH];  // fp16: particles @ W1[:16] + b1
__device__ __half g_P2h[BB * NN * HH];  // fp16: particles @ W1[16:]
__device__ float  g_rel[BB * NN * RR];  // scatter-add target (fp32)

// ---------------------------------------------------------------------------
// Kernel A: per-node first-layer projections (fp16 output) + zero rel.
// One thread per (b, n), 256-thread blocks, grid 128 (proven config).
// ---------------------------------------------------------------------------
__global__ __launch_bounds__(256) void node_proj_kernel(
    const float* __restrict__ particles,
    const float* __restrict__ W1,   // [32, 64] row-major
    const float* __restrict__ b1)   // [64]
{
    __shared__ float sW1[32 * 64];
    __shared__ float sb1[64];
    for (int i = threadIdx.x; i < 32 * 64; i += 256) sW1[i] = W1[i];
    if (threadIdx.x < 64) sb1[threadIdx.x] = b1[threadIdx.x];
    __syncthreads();

    int idx = blockIdx.x * 256 + threadIdx.x;  // 0 .. B*N-1

    float x[16];
    const float4* xp = (const float4*)(particles + (size_t)idx * 16);
    #pragma unroll
    for (int c = 0; c < 4; c++) {
        float4 v = xp[c];
        x[4 * c + 0] = v.x; x[4 * c + 1] = v.y; x[4 * c + 2] = v.z; x[4 * c + 3] = v.w;
    }

    uint2* P1o = (uint2*)(g_P1h + (size_t)idx * 64);
    uint2* P2o = (uint2*)(g_P2h + (size_t)idx * 64);

    #pragma unroll
    for (int c = 0; c < 16; c++) {
        float4 acc = ((const float4*)sb1)[c];
        #pragma unroll
        for (int i = 0; i < 16; i++) {
            float4 w = ((const float4*)(sW1 + i * 64))[c];
            acc.x += x[i] * w.x; acc.y += x[i] * w.y;
            acc.z += x[i] * w.z; acc.w += x[i] * w.w;
        }
        __half2 lo = __floats2half2_rn(acc.x, acc.y);
        __half2 hi = __floats2half2_rn(acc.z, acc.w);
        uint2 pkd;
        pkd.x = *reinterpret_cast<unsigned int*>(&lo);
        pkd.y = *reinterpret_cast<unsigned int*>(&hi);
        P1o[c] = pkd;
    }
    #pragma unroll
    for (int c = 0; c < 16; c++) {
        float4 acc = make_float4(0.f, 0.f, 0.f, 0.f);
        #pragma unroll
        for (int i = 0; i < 16; i++) {
            float4 w = ((const float4*)(sW1 + (16 + i) * 64))[c];
            acc.x += x[i] * w.x; acc.y += x[i] * w.y;
            acc.z += x[i] * w.z; acc.w += x[i] * w.w;
        }
        __half2 lo = __floats2half2_rn(acc.x, acc.y);
        __half2 hi = __floats2half2_rn(acc.z, acc.w);
        uint2 pkd;
        pkd.x = *reinterpret_cast<unsigned int*>(&lo);
        pkd.y = *reinterpret_cast<unsigned int*>(&hi);
        P2o[c] = pkd;
    }

    float4* relo = (float4*)(g_rel + (size_t)idx * 32);
    #pragma unroll
    for (int c = 0; c < 8; c++) relo[c] = make_float4(0.f, 0.f, 0.f, 0.f);
}

// ---------------------------------------------------------------------------
// Kernel B: edge MLP via wmma (HMMA tensor pipe). CTA = 256 thr / 8 warps;
// each warp owns 32 edges end-to-end:
//   gather: fp16 P rows (128B), ONE LDG.128 per (edge,side), shfl_xor(8)
//     combine, __hadd2/__hmax2 relu, STS.128 into per-warp h[32 x 72 halfs].
//   gemm: wmma 16x16x16 f16->f32. B = W2 fp16 (shared, ldm 32), 8 b-frags
//     loaded once. 2 Mt x 4 Kt x 2 Nt = 16 mma_sync.
//   epilogue: store_matrix_sync into the SAME per-warp buffer as
//     D[32 x 36 f32] (h dead, equal 4608B footprint); lane owns one edge:
//     +b2, relu, 8x red.global.add.v4.f32.
// ---------------------------------------------------------------------------
__global__ __launch_bounds__(256) void edge_kernel(
    const int* __restrict__ senders,
    const int* __restrict__ receivers,
    const float* __restrict__ W2,   // [64, 32] row-major
    const float* __restrict__ b2)   // [32]
{
    __shared__ __half sW2h[64 * 32];                 // 4KB, k-major rows
    __shared__ float  sb2[32];
    __shared__ __align__(16) char sBuf[8][32 * 144]; // per-warp h/D buffer
    __shared__ int    sS[256], sR[256];

    int tid  = threadIdx.x;
    int lane = tid & 31;
    int w    = tid >> 5;
    int base = blockIdx.x * 256;
    int b    = blockIdx.y;

    sS[tid] = senders[base + tid];
    sR[tid] = receivers[base + tid];
    for (int i = tid; i < 64 * 32; i += 256) sW2h[i] = __float2half(W2[i]);
    if (tid < 32) sb2[tid] = b2[tid];
    __syncthreads();   // only block-wide barrier

    const __half* P1b = g_P1h + (size_t)b * NN * 64;
    const __half* P2b = g_P2h + (size_t)b * NN * 64;

    // gather roles (R13-proven: 4 cache lines per warp inst)
    int half_ = (lane >> 4) & 1;    // which of 2 edges in this inst
    int side  = (lane >> 3) & 1;    // 0 = P1[sender], 1 = P2[receiver]
    int c     = lane & 7;           // 16B chunk of the 128B row
    const int*    myIdx = side ? sR : sS;
    const __half* myP   = side ? P2b : P1b;

    __half* hbuf = (__half*)sBuf[w];   // [32][72] halfs, 144B rows
    float*  dbuf = (float*) sBuf[w];   // [32][36] f32  (after gemm)

    const __half2 z2 = __float2half2_rn(0.f);

    // ---- gather: warp's 32 edges, 2 batches of 8 LDG.128 (MLP=8) ---------
    #pragma unroll
    for (int it0 = 0; it0 < 16; it0 += 8) {
        uint4 v[8];
        int   el[8];
        #pragma unroll
        for (int u = 0; u < 8; u++) {
            el[u] = (it0 + u) * 2 + half_;          // 0..31 (warp-local edge)
            int node = myIdx[w * 32 + el[u]];
            v[u] = *((const uint4*)(myP + (size_t)node * 64) + c);
        }
        #pragma unroll
        for (int u = 0; u < 8; u++) {
            uint4 p;
            p.x = __shfl_xor_sync(0xffffffffu, v[u].x, 8);
            p.y = __shfl_xor_sync(0xffffffffu, v[u].y, 8);
            p.z = __shfl_xor_sync(0xffffffffu, v[u].z, 8);
            p.w = __shfl_xor_sync(0xffffffffu, v[u].w, 8);
            if (side == 0) {
                __half2 h0 = __hmax2(__hadd2(*reinterpret_cast<__half2*>(&v[u].x),
                                             *reinterpret_cast<__half2*>(&p.x)), z2);
                __half2 h1 = __hmax2(__hadd2(*reinterpret_cast<__half2*>(&v[u].y),
                                             *reinterpret_cast<__half2*>(&p.y)), z2);
                __half2 h2 = __hmax2(__hadd2(*reinterpret_cast<__half2*>(&v[u].z),
                                             *reinterpret_cast<__half2*>(&p.z)), z2);
                __half2 h3 = __hmax2(__hadd2(*reinterpret_cast<__half2*>(&v[u].w),
                                             *reinterpret_cast<__half2*>(&p.w)), z2);
                uint4 o;
                o.x = *reinterpret_cast<unsigned int*>(&h0);
                o.y = *reinterpret_cast<unsigned int*>(&h1);
                o.z = *reinterpret_cast<unsigned int*>(&h2);
                o.w = *reinterpret_cast<unsigned int*>(&h3);
                // h row el[u], halfs 8c..8c+7 -> byte 144*el + 16*c (aligned)
                *reinterpret_cast<uint4*>((char*)hbuf + el[u] * 144 + c * 16) = o;
            }
        }
    }
    __syncwarp();

    // ---- gemm: D[32x32] = h[32x64] @ W2[64x32], wmma f16 -> f32 ----------
    wmma::fragment<wmma::matrix_b, 16, 16, 16, __half, wmma::row_major> bf[4][2];
    #pragma unroll
    for (int kt = 0; kt < 4; kt++)
        #pragma unroll
        for (int nt = 0; nt < 2; nt++)
            wmma::load_matrix_sync(bf[kt][nt], &sW2h[kt * 16 * 32 + nt * 16], 32);

    wmma::fragment<wmma::accumulator, 16, 16, 16, float> accf[2][2];
    #pragma unroll
    for (int mt = 0; mt < 2; mt++)
        #pragma unroll
        for (int nt = 0; nt < 2; nt++)
            wmma::fill_fragment(accf[mt][nt], 0.0f);

    #pragma unroll
    for (int mt = 0; mt < 2; mt++) {
        #pragma unroll
        for (int kt = 0; kt < 4; kt++) {
            wmma::fragment<wmma::matrix_a, 16, 16, 16, __half, wmma::row_major> af;
            wmma::load_matrix_sync(af, hbuf + mt * 16 * 72 + kt * 16, 72);
            #pragma unroll
            for (int nt = 0; nt < 2; nt++)
                wmma::mma_sync(accf[mt][nt], af, bf[kt][nt], accf[mt][nt]);
        }
    }
    __syncwarp();

    // ---- store D into the same buffer (h is dead), stride 36 f32 ---------
    #pragma unroll
    for (int mt = 0; mt < 2; mt++)
        #pragma unroll
        for (int nt = 0; nt < 2; nt++)
            wmma::store_matrix_sync(dbuf + mt * 16 * 36 + nt * 16,
                                    accf[mt][nt], 36, wmma::mem_row_major);
    __syncwarp();

    // ---- epilogue: lane owns edge w*32+lane: +b2, relu, 8x red.v4 --------
    {
        int r = sR[w * 32 + lane];
        float* ptr = g_rel + (size_t)b * NN * 32 + (size_t)r * 32;
        const float* drow = dbuf + lane * 36;
        #pragma unroll
        for (int q = 0; q < 8; q++) {
            float4 dv = *(const float4*)(drow + 4 * q);
            float4 bv = *(const float4*)(sb2 + 4 * q);
            float f0 = fmaxf(dv.x + bv.x, 0.f);
            float f1 = fmaxf(dv.y + bv.y, 0.f);
            float f2 = fmaxf(dv.z + bv.z, 0.f);
            float f3 = fmaxf(dv.w + bv.w, 0.f);
            asm volatile("red.global.add.v4.f32 [%0], {%1, %2, %3, %4};"
                         :: "l"(ptr + 4 * q), "f"(f0), "f"(f1), "f"(f2), "f"(f3)
                         : "memory");
        }
    }
}

// ---------------------------------------------------------------------------
// Kernel C (R3-proven config): node MLP + residual. One thread per (b, n).
// ---------------------------------------------------------------------------
__global__ __launch_bounds__(256) void node_out_kernel(
    const float* __restrict__ particles,
    const float* __restrict__ W3,   // [48, 64]
    const float* __restrict__ b3,   // [64]
    const float* __restrict__ W4,   // [64, 16]
    const float* __restrict__ b4,   // [16]
    float* __restrict__ out)
{
    __shared__ float sW3[48 * 64];
    __shared__ float sW4[64 * 16];
    __shared__ float sb3[64];
    __shared__ float sb4[16];
    for (int i = threadIdx.x; i < 48 * 64; i += 256) sW3[i] = W3[i];
    for (int i = threadIdx.x; i < 64 * 16; i += 256) sW4[i] = W4[i];
    if (threadIdx.x < 64) sb3[threadIdx.x] = b3[threadIdx.x];
    if (threadIdx.x < 16) sb4[threadIdx.x] = b4[threadIdx.x];
    __syncthreads();

    int idx = blockIdx.x * 256 + threadIdx.x;

    float x[48];
    const float4* pp = (const float4*)(particles + (size_t)idx * 16);
    #pragma unroll
    for (int c = 0; c < 4; c++) {
        float4 v = pp[c];
        x[4 * c + 0] = v.x; x[4 * c + 1] = v.y; x[4 * c + 2] = v.z; x[4 * c + 3] = v.w;
    }
    const float4* rp = (const float4*)(g_rel + (size_t)idx * 32);
    #pragma unroll
    for (int c = 0; c < 8; c++) {
        float4 v = rp[c];
        x[16 + 4 * c + 0] = v.x; x[16 + 4 * c + 1] = v.y;
        x[16 + 4 * c + 2] = v.z; x[16 + 4 * c + 3] = v.w;
    }

    float delta[16];
    #pragma unroll
    for (int j = 0; j < 16; j++) delta[j] = sb4[j];

    #pragma unroll
    for (int half = 0; half < 2; half++) {
        float t[32];
        #pragma unroll
        for (int j = 0; j < 32; j++) t[j] = sb3[half * 32 + j];

        #pragma unroll
        for (int i = 0; i < 48; i++) {
            const float4* w = (const float4*)(sW3 + i * 64 + half * 32);
            float xv = x[i];
            #pragma unroll
            for (int j = 0; j < 8; j++) {
                float4 wv = w[j];
                t[4 * j + 0] += xv * wv.x;
                t[4 * j + 1] += xv * wv.y;
                t[4 * j + 2] += xv * wv.z;
                t[4 * j + 3] += xv * wv.w;
            }
        }
        #pragma unroll
        for (int j = 0; j < 32; j++) t[j] = fmaxf(t[j], 0.f);

        #pragma unroll
        for (int i = 0; i < 32; i++) {
            const float4* w = (const float4*)(sW4 + (half * 32 + i) * 16);
            float tv = t[i];
            #pragma unroll
            for (int j = 0; j < 4; j++) {
                float4 wv = w[j];
                delta[4 * j + 0] += tv * wv.x;
                delta[4 * j + 1] += tv * wv.y;
                delta[4 * j + 2] += tv * wv.z;
                delta[4 * j + 3] += tv * wv.w;
            }
        }
    }

    float4* outp = (float4*)(out + (size_t)idx * 16);
    #pragma unroll
    for (int c = 0; c < 4; c++) {
        outp[c] = make_float4(x[4 * c + 0] + delta[4 * c + 0],
                              x[4 * c + 1] + delta[4 * c + 1],
                              x[4 * c + 2] + delta[4 * c + 2],
                              x[4 * c + 3] + delta[4 * c + 3]);
    }
}

extern "C" void kernel_launch(void* const* d_in, const int* in_sizes, int n_in,
                              void* d_out, int out_size)
{
    const float* particles = (const float*)d_in[0];
    const int*   senders   = (const int*)d_in[1];
    const int*   receivers = (const int*)d_in[2];
    const float* W1 = (const float*)d_in[3];
    const float* b1 = (const float*)d_in[4];
    const float* W2 = (const float*)d_in[5];
    const float* b2 = (const float*)d_in[6];
    const float* W3 = (const float*)d_in[7];
    const float* b3 = (const float*)d_in[8];
    const float* W4 = (const float*)d_in[9];
    const float* b4 = (const float*)d_in[10];
    float* out = (float*)d_out;

    node_proj_kernel<<<(BB * NN) / 256, 256>>>(particles, W1, b1);

    dim3 egrid(EE / 256, BB);
    edge_kernel<<<egrid, 256>>>(senders, receivers, W2, b2);

    node_out_kernel<<<(BB * NN) / 256, 256>>>(particles, W3, b3, W4, b4, out);
}

// round 16
// speedup vs baseline: 1.4232x; 1.4232x over previous
#include <cuda_runtime.h>
#include <cuda_fp16.h>
#include <mma.h>
#include <cstdint>

using namespace nvcuda;

#define BB 4
#define NN 8192
#define DD 16
#define RR 32
#define HH 64
#define EE 262144

// Scratch (allocation-free: __device__ globals)
__device__ __half g_P1h[BB * NN * HH];  // fp16: particles @ W1[:16] + b1
__device__ __half g_P2h[BB * NN * HH];  // fp16: particles @ W1[16:]
__device__ float  g_rel[BB * NN * RR];  // per-receiver aggregate (fp32)
__device__ int    g_counts[NN];         // receiver degree histogram
__device__ int    g_offs[NN + 1];       // CSR offsets
__device__ int    g_cursors[NN];        // fill cursors
__device__ int    g_sortedS[EE];        // sender ids, grouped by receiver

// ---------------------------------------------------------------------------
// Prep 1: zero histogram
// ---------------------------------------------------------------------------
__global__ void zero_counts_kernel() {
    int i = blockIdx.x * 256 + threadIdx.x;
    if (i < NN) g_counts[i] = 0;
}

// ---------------------------------------------------------------------------
// Prep 2: histogram receivers
// ---------------------------------------------------------------------------
__global__ void hist_kernel(const int* __restrict__ receivers) {
    int e = blockIdx.x * 256 + threadIdx.x;
    atomicAdd(&g_counts[receivers[e]], 1);
}

// ---------------------------------------------------------------------------
// Prep 3: exclusive scan of 8192 counts (single block, 1024 threads)
// ---------------------------------------------------------------------------
__global__ __launch_bounds__(1024) void scan_kernel() {
    __shared__ int sPart[1024];
    int t = threadIdx.x;
    int base = t * 8;
    int c[8], run = 0;
    #pragma unroll
    for (int i = 0; i < 8; i++) {
        int v = g_counts[base + i];
        c[i] = run;           // exclusive within chunk
        run += v;
    }
    sPart[t] = run;
    __syncthreads();
    for (int off = 1; off < 1024; off <<= 1) {
        int v = (t >= off) ? sPart[t - off] : 0;
        __syncthreads();
        sPart[t] += v;
        __syncthreads();
    }
    int prev = (t == 0) ? 0 : sPart[t - 1];
    #pragma unroll
    for (int i = 0; i < 8; i++) {
        int o = prev + c[i];
        g_offs[base + i]    = o;
        g_cursors[base + i] = o;
    }
    if (t == 1023) g_offs[NN] = sPart[1023];
}

// ---------------------------------------------------------------------------
// Prep 4: fill sorted sender list (grouped by receiver)
// ---------------------------------------------------------------------------
__global__ void fill_kernel(const int* __restrict__ senders,
                            const int* __restrict__ receivers) {
    int e = blockIdx.x * 256 + threadIdx.x;
    int r = receivers[e];
    int p = atomicAdd(&g_cursors[r], 1);
    g_sortedS[p] = senders[e];
}

// ---------------------------------------------------------------------------
// Kernel A: per-node first-layer projections (fp16 output).
// One thread per (b, n), 256-thread blocks, grid 128 (proven config).
// ---------------------------------------------------------------------------
__global__ __launch_bounds__(256) void node_proj_kernel(
    const float* __restrict__ particles,
    const float* __restrict__ W1,   // [32, 64] row-major
    const float* __restrict__ b1)   // [64]
{
    __shared__ float sW1[32 * 64];
    __shared__ float sb1[64];
    for (int i = threadIdx.x; i < 32 * 64; i += 256) sW1[i] = W1[i];
    if (threadIdx.x < 64) sb1[threadIdx.x] = b1[threadIdx.x];
    __syncthreads();

    int idx = blockIdx.x * 256 + threadIdx.x;  // 0 .. B*N-1

    float x[16];
    const float4* xp = (const float4*)(particles + (size_t)idx * 16);
    #pragma unroll
    for (int c = 0; c < 4; c++) {
        float4 v = xp[c];
        x[4 * c + 0] = v.x; x[4 * c + 1] = v.y; x[4 * c + 2] = v.z; x[4 * c + 3] = v.w;
    }

    uint2* P1o = (uint2*)(g_P1h + (size_t)idx * 64);
    uint2* P2o = (uint2*)(g_P2h + (size_t)idx * 64);

    #pragma unroll
    for (int c = 0; c < 16; c++) {
        float4 acc = ((const float4*)sb1)[c];
        #pragma unroll
        for (int i = 0; i < 16; i++) {
            float4 w = ((const float4*)(sW1 + i * 64))[c];
            acc.x += x[i] * w.x; acc.y += x[i] * w.y;
            acc.z += x[i] * w.z; acc.w += x[i] * w.w;
        }
        __half2 lo = __floats2half2_rn(acc.x, acc.y);
        __half2 hi = __floats2half2_rn(acc.z, acc.w);
        uint2 pkd;
        pkd.x = *reinterpret_cast<unsigned int*>(&lo);
        pkd.y = *reinterpret_cast<unsigned int*>(&hi);
        P1o[c] = pkd;
    }
    #pragma unroll
    for (int c = 0; c < 16; c++) {
        float4 acc = make_float4(0.f, 0.f, 0.f, 0.f);
        #pragma unroll
        for (int i = 0; i < 16; i++) {
            float4 w = ((const float4*)(sW1 + (16 + i) * 64))[c];
            acc.x += x[i] * w.x; acc.y += x[i] * w.y;
            acc.z += x[i] * w.z; acc.w += x[i] * w.w;
        }
        __half2 lo = __floats2half2_rn(acc.x, acc.y);
        __half2 hi = __floats2half2_rn(acc.z, acc.w);
        uint2 pkd;
        pkd.x = *reinterpret_cast<unsigned int*>(&lo);
        pkd.y = *reinterpret_cast<unsigned int*>(&hi);
        P2o[c] = pkd;
    }
}

// ---------------------------------------------------------------------------
// Kernel B: edge MLP, CSR-by-receiver, ATOMIC-FREE. One warp per
// (receiver, batch); CTA = 256 thr / 8 warps.
//   - P2[r] row loaded ONCE per warp (lane keeps its 16B chunk in a reg).
//   - per 32-edge tile: cooperative gather of P1 rows (4 rows / inst),
//     h = relu(P1[s] + P2[r]) fp16 -> per-warp hbuf [32 x 72 halfs].
//   - wmma GEMM h[32x64] @ W2[64x32] -> dbuf [32 x 36 f32] (same buffer).
//   - column-reduce over valid rows: acc_j += relu(dbuf[i][j] + b2[j]).
//   - ONE plain coalesced 32-float store to g_rel[b][r]. No atomics.
// ---------------------------------------------------------------------------
__global__ __launch_bounds__(256) void edge_kernel(
    const float* __restrict__ W2,   // [64, 32] row-major
    const float* __restrict__ b2)   // [32]
{
    __shared__ __half sW2h[64 * 32];                 // 4KB
    __shared__ __align__(16) char sBuf[8][32 * 144]; // per-warp h/D buffer

    int tid  = threadIdx.x;
    int lane = tid & 31;
    int w    = tid >> 5;

    for (int i = tid; i < 64 * 32; i += 256) sW2h[i] = __float2half(W2[i]);
    __syncthreads();

    int gw = blockIdx.x * 8 + w;        // 0 .. 4*8192-1
    int r  = gw & (NN - 1);
    int b  = gw >> 13;

    const __half* P1b = g_P1h + (size_t)b * NN * 64;
    const __half* P2b = g_P2h + (size_t)b * NN * 64;

    int start = g_offs[r];
    int end   = g_offs[r + 1];

    // P2[r] chunk for this lane (fixed: lane & 7)
    int c = lane & 7;
    uint4 p2c = *((const uint4*)(P2b + (size_t)r * 64) + c);
    float b2j = b2[lane];

    __half* hbuf = (__half*)sBuf[w];    // [32][72] halfs (144B rows)
    float*  dbuf = (float*) sBuf[w];    // [32][36] f32 (aliases hbuf)

    const __half2 z2 = __float2half2_rn(0.f);
    float acc = 0.f;

    for (int tb = start; tb < end; tb += 32) {
        int cnt = min(32, end - tb);

        // sender ids for this tile (lane l holds id of tile-edge l)
        int idreg = (lane < cnt) ? g_sortedS[tb + lane] : 0;

        // ---- gather: 8 insts cover 32 edge rows (4 rows / inst) ----------
        #pragma unroll
        for (int u = 0; u < 8; u++) {
            int esub = u * 4 + (lane >> 3);              // 0..31
            int s = __shfl_sync(0xffffffffu, idreg, esub);
            uint4 v = *((const uint4*)(P1b + (size_t)s * 64) + c);
            __half2 h0 = __hmax2(__hadd2(*reinterpret_cast<__half2*>(&v.x),
                                         *reinterpret_cast<const __half2*>(&p2c.x)), z2);
            __half2 h1 = __hmax2(__hadd2(*reinterpret_cast<__half2*>(&v.y),
                                         *reinterpret_cast<const __half2*>(&p2c.y)), z2);
            __half2 h2 = __hmax2(__hadd2(*reinterpret_cast<__half2*>(&v.z),
                                         *reinterpret_cast<const __half2*>(&p2c.z)), z2);
            __half2 h3 = __hmax2(__hadd2(*reinterpret_cast<__half2*>(&v.w),
                                         *reinterpret_cast<const __half2*>(&p2c.w)), z2);
            uint4 o;
            o.x = *reinterpret_cast<unsigned int*>(&h0);
            o.y = *reinterpret_cast<unsigned int*>(&h1);
            o.z = *reinterpret_cast<unsigned int*>(&h2);
            o.w = *reinterpret_cast<unsigned int*>(&h3);
            *reinterpret_cast<uint4*>((char*)hbuf + esub * 144 + c * 16) = o;
        }
        __syncwarp();

        // ---- gemm: D[32x32] = h[32x64] @ W2[64x32] -----------------------
        wmma::fragment<wmma::accumulator, 16, 16, 16, float> accf[2][2];
        #pragma unroll
        for (int mt = 0; mt < 2; mt++)
            #pragma unroll
            for (int nt = 0; nt < 2; nt++)
                wmma::fill_fragment(accf[mt][nt], 0.0f);

        #pragma unroll
        for (int kt = 0; kt < 4; kt++) {
            wmma::fragment<wmma::matrix_b, 16, 16, 16, __half, wmma::row_major> bf0, bf1;
            wmma::load_matrix_sync(bf0, &sW2h[kt * 16 * 32 + 0], 32);
            wmma::load_matrix_sync(bf1, &sW2h[kt * 16 * 32 + 16], 32);
            #pragma unroll
            for (int mt = 0; mt < 2; mt++) {
                wmma::fragment<wmma::matrix_a, 16, 16, 16, __half, wmma::row_major> af;
                wmma::load_matrix_sync(af, hbuf + mt * 16 * 72 + kt * 16, 72);
                wmma::mma_sync(accf[mt][0], af, bf0, accf[mt][0]);
                wmma::mma_sync(accf[mt][1], af, bf1, accf[mt][1]);
            }
        }
        __syncwarp();

        #pragma unroll
        for (int mt = 0; mt < 2; mt++)
            #pragma unroll
            for (int nt = 0; nt < 2; nt++)
                wmma::store_matrix_sync(dbuf + mt * 16 * 36 + nt * 16,
                                        accf[mt][nt], 36, wmma::mem_row_major);
        __syncwarp();

        // ---- column reduce over valid rows: lane = column ----------------
        {
            float a0 = 0.f, a1 = 0.f, a2 = 0.f, a3 = 0.f;
            int i = 0;
            for (; i + 4 <= cnt; i += 4) {
                a0 += fmaxf(dbuf[(i + 0) * 36 + lane] + b2j, 0.f);
                a1 += fmaxf(dbuf[(i + 1) * 36 + lane] + b2j, 0.f);
                a2 += fmaxf(dbuf[(i + 2) * 36 + lane] + b2j, 0.f);
                a3 += fmaxf(dbuf[(i + 3) * 36 + lane] + b2j, 0.f);
            }
            for (; i < cnt; i++)
                a0 += fmaxf(dbuf[i * 36 + lane] + b2j, 0.f);
            acc += (a0 + a1) + (a2 + a3);
        }
        __syncwarp();   // dbuf reused as hbuf next tile
    }

    // ---- exclusive ownership: plain coalesced store, NO atomics ----------
    g_rel[((size_t)b * NN + r) * 32 + lane] = acc;
}

// ---------------------------------------------------------------------------
// Kernel C (R3-proven config): node MLP + residual. One thread per (b, n).
// ---------------------------------------------------------------------------
__global__ __launch_bounds__(256) void node_out_kernel(
    const float* __restrict__ particles,
    const float* __restrict__ W3,   // [48, 64]
    const float* __restrict__ b3,   // [64]
    const float* __restrict__ W4,   // [64, 16]
    const float* __restrict__ b4,   // [16]
    float* __restrict__ out)
{
    __shared__ float sW3[48 * 64];
    __shared__ float sW4[64 * 16];
    __shared__ float sb3[64];
    __shared__ float sb4[16];
    for (int i = threadIdx.x; i < 48 * 64; i += 256) sW3[i] = W3[i];
    for (int i = threadIdx.x; i < 64 * 16; i += 256) sW4[i] = W4[i];
    if (threadIdx.x < 64) sb3[threadIdx.x] = b3[threadIdx.x];
    if (threadIdx.x < 16) sb4[threadIdx.x] = b4[threadIdx.x];
    __syncthreads();

    int idx = blockIdx.x * 256 + threadIdx.x;

    float x[48];
    const float4* pp = (const float4*)(particles + (size_t)idx * 16);
    #pragma unroll
    for (int c = 0; c < 4; c++) {
        float4 v = pp[c];
        x[4 * c + 0] = v.x; x[4 * c + 1] = v.y; x[4 * c + 2] = v.z; x[4 * c + 3] = v.w;
    }
    const float4* rp = (const float4*)(g_rel + (size_t)idx * 32);
    #pragma unroll
    for (int c = 0; c < 8; c++) {
        float4 v = rp[c];
        x[16 + 4 * c + 0] = v.x; x[16 + 4 * c + 1] = v.y;
        x[16 + 4 * c + 2] = v.z; x[16 + 4 * c + 3] = v.w;
    }

    float delta[16];
    #pragma unroll
    for (int j = 0; j < 16; j++) delta[j] = sb4[j];

    #pragma unroll
    for (int half = 0; half < 2; half++) {
        float t[32];
        #pragma unroll
        for (int j = 0; j < 32; j++) t[j] = sb3[half * 32 + j];

        #pragma unroll
        for (int i = 0; i < 48; i++) {
            const float4* w = (const float4*)(sW3 + i * 64 + half * 32);
            float xv = x[i];
            #pragma unroll
            for (int j = 0; j < 8; j++) {
                float4 wv = w[j];
                t[4 * j + 0] += xv * wv.x;
                t[4 * j + 1] += xv * wv.y;
                t[4 * j + 2] += xv * wv.z;
                t[4 * j + 3] += xv * wv.w;
            }
        }
        #pragma unroll
        for (int j = 0; j < 32; j++) t[j] = fmaxf(t[j], 0.f);

        #pragma unroll
        for (int i = 0; i < 32; i++) {
            const float4* w = (const float4*)(sW4 + (half * 32 + i) * 16);
            float tv = t[i];
            #pragma unroll
            for (int j = 0; j < 4; j++) {
                float4 wv = w[j];
                delta[4 * j + 0] += tv * wv.x;
                delta[4 * j + 1] += tv * wv.y;
                delta[4 * j + 2] += tv * wv.z;
                delta[4 * j + 3] += tv * wv.w;
            }
        }
    }

    float4* outp = (float4*)(out + (size_t)idx * 16);
    #pragma unroll
    for (int c = 0; c < 4; c++) {
        outp[c] = make_float4(x[4 * c + 0] + delta[4 * c + 0],
                              x[4 * c + 1] + delta[4 * c + 1],
                              x[4 * c + 2] + delta[4 * c + 2],
                              x[4 * c + 3] + delta[4 * c + 3]);
    }
}

extern "C" void kernel_launch(void* const* d_in, const int* in_sizes, int n_in,
                              void* d_out, int out_size)
{
    const float* particles = (const float*)d_in[0];
    const int*   senders   = (const int*)d_in[1];
    const int*   receivers = (const int*)d_in[2];
    const float* W1 = (const float*)d_in[3];
    const float* b1 = (const float*)d_in[4];
    const float* W2 = (const float*)d_in[5];
    const float* b2 = (const float*)d_in[6];
    const float* W3 = (const float*)d_in[7];
    const float* b3 = (const float*)d_in[8];
    const float* W4 = (const float*)d_in[9];
    const float* b4 = (const float*)d_in[10];
    float* out = (float*)d_out;

    // CSR prep (receivers/senders are launch inputs; rebuilt every call)
    zero_counts_kernel<<<NN / 256, 256>>>();
    hist_kernel<<<EE / 256, 256>>>(receivers);
    scan_kernel<<<1, 1024>>>();
    fill_kernel<<<EE / 256, 256>>>(senders, receivers);

    node_proj_kernel<<<(BB * NN) / 256, 256>>>(particles, W1, b1);

    edge_kernel<<<(BB * NN) / 8, 256>>>(W2, b2);

    node_out_kernel<<<(BB * NN) / 256, 256>>>(particles, W3, b3, W4, b4, out);
}